// round 15
// baseline (speedup 1.0000x reference)
#include <cuda_runtime.h>
#include <math.h>

#define L_SEQ 32768
#define H_DIM 128
#define P_DIM 256
#define CHUNK 64
#define NCHUNK (L_SEQ / CHUNK)   // 512
#define PTILE 64
#define BUS 136                   // padded float stride of Bu tile in smem

typedef unsigned long long u64;
typedef unsigned int u32;

// ---------- cp.async helpers ----------
__device__ __forceinline__ void s5_cp16(void* dst, const void* src) {
    unsigned d = (unsigned)__cvta_generic_to_shared(dst);
    asm volatile("cp.async.cg.shared.global [%0], [%1], 16;" :: "r"(d), "l"(src));
}
__device__ __forceinline__ void s5_cpcommit() {
    asm volatile("cp.async.commit_group;");
}
template <int N>
__device__ __forceinline__ void s5_cpwait() {
    asm volatile("cp.async.wait_group %0;" :: "n"(N));
}

// ---------- tf32 helpers ----------
__device__ __forceinline__ float s5_tf32_rna(float v) {
    u32 h;
    asm("cvt.rna.tf32.f32 %0, %1;" : "=r"(h) : "f"(v));
    return __uint_as_float(h);
}
#define S5_MMA(d, a, b0v, b1v) \
    asm volatile("mma.sync.aligned.m16n8k8.row.col.f32.tf32.tf32.f32 " \
                 "{%0,%1,%2,%3},{%4,%5,%6,%7},{%8,%9},{%0,%1,%2,%3};" \
                 : "+f"((d)[0]), "+f"((d)[1]), "+f"((d)[2]), "+f"((d)[3]) \
                 : "r"((a)[0]), "r"((a)[1]), "r"((a)[2]), "r"((a)[3]), \
                   "r"(b0v), "r"(b1v))

// ---------- fast math (validated ranges) ----------
__device__ __forceinline__ float s5_exp_small(float x) {   // x in [-0.06, 0]
    return fmaf(x, fmaf(x, fmaf(x, fmaf(x, 0.041666667f, 0.16666667f), 0.5f), 1.0f), 1.0f);
}
__device__ __forceinline__ void s5_sincos2(float x, float xlo, float& s_out, float& c_out) {
    float kf = rintf(x * 0.636619772f);                 // 2/pi
    float r = fmaf(-kf, 1.57079637f, x);
    r = fmaf(kf, 4.37113900e-8f, r);
    r += xlo;
    int q = (int)kf;
    float r2 = r * r;
    float sp = fmaf(r2, fmaf(r2, fmaf(r2, 2.7557314e-6f, -1.9841270e-4f),
                             8.3333310e-3f), -0.16666667f);
    sp = fmaf(r * r2, sp, r);
    float cp = fmaf(r2, fmaf(r2, fmaf(r2, 2.4801587e-5f, -1.3888889e-3f),
                             4.1666668e-2f), -0.5f);
    cp = fmaf(r2, cp, 1.0f);
    bool swp = (q & 1);
    float ss = swp ? cp : sp;
    float cc = swp ? sp : cp;
    if (q & 2) ss = -ss;
    if ((q + 1) & 2) cc = -cc;
    s_out = ss; c_out = cc;
}
__device__ __forceinline__ void s5_sincos(float x, float& s_out, float& c_out) {
    s5_sincos2(x, 0.0f, s_out, c_out);
}

// ---------- scratch (static device memory; no allocations) ----------
__device__ __align__(16) float2 sc_xloc[(size_t)L_SEQ * P_DIM];   // 64 MB
__device__ __align__(16) float2 sc_AchunkT[P_DIM * NCHUNK];       // [p][chunk]
__device__ __align__(16) float2 sc_xendT[P_DIM * NCHUNK];         // [p][chunk]
__device__ __align__(16) float2 sc_carry[NCHUNK * P_DIM];         // [chunk][p]
__device__ __align__(16) float2 sc_S[NCHUNK * CHUNK];             // dt prefix sums (hi, lo)
__device__ __align__(16) float4 sc_ab4[P_DIM];                    // (alpha, beta_hi, beta_lo, 0)
// k3 tensor operand: W = [2*Cr ; -2*Ci], tf32-RNE, fragment-permuted
__device__ __align__(16) float sc_Wt[16 * 4 * H_DIM * 8];         // 256 KB
// k1 tensor operand: WB[ptile(4)][s(4)][k8(4)][col(128)][sub(8)], col = 2*pl + (re/im)
__device__ __align__(16) float sc_WB[4 * 4 * 4 * 128 * 8];        // 256 KB

// ---------- S0: pack/permute operands; per-p discretization params ----------
__global__ void s5_k0_pack(const float* __restrict__ Br, const float* __restrict__ Bi,
                           const float* __restrict__ Cr, const float* __restrict__ Ci,
                           const float* __restrict__ Lre, const float* __restrict__ Lim,
                           const float* __restrict__ logstep) {
    int idx = blockIdx.x * blockDim.x + threadIdx.x;
    if (idx < H_DIM * P_DIM) {
        int h = idx & 127, p = idx >> 7;
        {   // Wt (k3 operand)
            int s = p >> 4, pp = p & 15;
            int c = pp & 7;
            int sub = (c & 3) * 2 + (c >> 2);
            int k8r = pp >> 3;
            int k8i = 2 + (pp >> 3);
            float cr = Cr[h * P_DIM + p];
            float ci = Ci[h * P_DIM + p];
            sc_Wt[s * 4096 + k8r * 1024 + h * 8 + sub] = s5_tf32_rna(2.0f * cr);
            sc_Wt[s * 4096 + k8i * 1024 + h * 8 + sub] = s5_tf32_rna(-2.0f * ci);
        }
        {   // WB (k1 operand)
            int pt = p >> 6, pl = p & 63;
            int s = h >> 5, hk = h & 31;
            int k8 = hk >> 3, c = hk & 7;
            int sub = (c & 3) * 2 + (c >> 2);
            size_t base = ((size_t)(pt * 4 + s) * 4 + k8) * 1024;
            sc_WB[base + (pl * 2 + 0) * 8 + sub] = s5_tf32_rna(Br[p * H_DIM + h]);
            sc_WB[base + (pl * 2 + 1) * 8 + sub] = s5_tf32_rna(Bi[p * H_DIM + h]);
        }
        if (idx < P_DIM) {
            float step = expf(logstep[idx]);
            float a  = Lre[idx] * step;
            float bh = Lim[idx] * step;
            float bl = fmaf(Lim[idx], step, -bh);
            sc_ab4[idx] = make_float4(a, bh, bl, 0.0f);
        }
    }
}

// ---------- S0b: per-chunk dt prefix sums in fp64, stored hi/lo ----------
__global__ void s5_kS_prefix(const float* __restrict__ dts) {
    __shared__ double s[CHUNK];
    int c = blockIdx.x, t = threadIdx.x;
    s[t] = (double)dts[c * CHUNK + t];
    __syncthreads();
#pragma unroll
    for (int off = 1; off < CHUNK; off <<= 1) {
        double add = (t >= off) ? s[t - off] : 0.0;
        __syncthreads();
        s[t] += add;
        __syncthreads();
    }
    double Sd = s[t];
    float hi = (float)Sd;
    float lo = (float)(Sd - (double)hi);
    sc_S[c * CHUNK + t] = make_float2(hi, lo);
}

// ---------- S1: TENSOR Bu = u @ [Br|Bi]^T, then 4-way-parallel local scan ----------
__global__ __launch_bounds__(256, 2) void s5_k1_gemm_scan(
    const float* __restrict__ u, const float* __restrict__ dts,
    const float* __restrict__ Lre, const float* __restrict__ Lim,
    const float* __restrict__ logstep) {
    __shared__ __align__(16) char smem[40960];
    float* xs  = (float*)smem;                        // u hi [0,8192)
    float* wB0 = (float*)(smem + 8192);               // WB slice buf 0 (16 KB)
    float* wB1 = (float*)(smem + 24576);
    // scan-phase aliases
    float* Bu_s  = (float*)smem;                      // 64 x BUS floats (34816 B)
    float* dt_s  = (float*)(smem + 34816);            // 256 B
    float2* As_s  = (float2*)(smem + 35072);          // 2 KB
    float2* xs_s2 = (float2*)(smem + 37120);          // 2 KB

    int tid = threadIdx.x;
    int lane = tid & 31, wid = tid >> 5;
    int gid = lane >> 2, tig = lane & 3;
    int wm = wid & 3, wn = wid >> 2;
    int l0 = blockIdx.y * CHUNK;
    int pt = blockIdx.x;
    int p0 = pt * PTILE;

    float d[8][4];
#pragma unroll
    for (int j = 0; j < 8; j++)
#pragma unroll
        for (int i = 0; i < 4; i++) d[j][i] = 0.0f;

    float ur[8];
    auto ldgU = [&](int s) {
        int h0 = s * 32;
#pragma unroll
        for (int e = 0; e < 8; e++) {
            int idx = e * 256 + tid;
            int row = idx >> 5, k = idx & 31;
            ur[e] = u[(size_t)(l0 + row) * H_DIM + h0 + k];
        }
    };
    auto stU = [&]() {
#pragma unroll
        for (int e = 0; e < 8; e++) {
            int idx = e * 256 + tid;
            int row = idx >> 5, k = idx & 31;
            int c = k & 7;
            int off = (k >> 3) * 512 + row * 8 + (c & 3) * 2 + (c >> 2);
            xs[off] = s5_tf32_rna(ur[e]);
        }
    };
    auto cpW = [&](int s, int b) {
        float* wb = b ? wB1 : wB0;
        const float* src = &sc_WB[(size_t)(pt * 4 + s) * 4096];
#pragma unroll
        for (int e = 0; e < 4; e++) {
            int q = e * 256 + tid;
            s5_cp16(&wb[q * 4], &src[q * 4]);
        }
        s5_cpcommit();
    };

    ldgU(0);
    cpW(0, 0);
#pragma unroll
    for (int s = 0; s < 4; s++) {
        int b = s & 1;
        stU();
        if (s < 3) { ldgU(s + 1); cpW(s + 1, b ^ 1); }
        if (s < 3) s5_cpwait<1>(); else s5_cpwait<0>();
        __syncthreads();
        const float* wb = b ? wB1 : wB0;
#pragma unroll
        for (int k8 = 0; k8 < 4; k8++) {
            int arow = wm * 16 + gid;
            float2 ah0 = *(const float2*)(xs + k8 * 512 + arow * 8 + tig * 2);
            float2 ah1 = *(const float2*)(xs + k8 * 512 + (arow + 8) * 8 + tig * 2);
            u32 ahi[4] = {__float_as_uint(ah0.x), __float_as_uint(ah1.x),
                          __float_as_uint(ah0.y), __float_as_uint(ah1.y)};
#pragma unroll
            for (int j = 0; j < 8; j++) {
                float2 bv = *(const float2*)(wb + k8 * 1024 + (wn * 64 + j * 8 + gid) * 8 + tig * 2);
                S5_MMA(d[j], ahi, __float_as_uint(bv.x), __float_as_uint(bv.y));
            }
        }
        __syncthreads();
    }

    // write Bu tile into padded smem + dt
#pragma unroll
    for (int j = 0; j < 8; j++) {
        int cc = wn * 64 + j * 8 + tig * 2;
        int r1 = wm * 16 + gid;
        *(float2*)(Bu_s + r1 * BUS + cc)       = make_float2(d[j][0], d[j][1]);
        *(float2*)(Bu_s + (r1 + 8) * BUS + cc) = make_float2(d[j][2], d[j][3]);
    }
    if (tid < CHUNK) dt_s[tid] = dts[l0 + tid];
    __syncthreads();

    // ---- parallel local scan: 64 p-columns x 4 segments of 16 steps ----
    int p   = tid & 63;
    int seg = tid >> 6;
    int gp  = p0 + p;
    int lb  = seg * 16;
    float lre = Lre[gp], lim = Lim[gp];
    float step = expf(logstep[gp]);
    float inv = 1.0f / (lre * lre + lim * lim);

    float xrA[16], xiA[16], ArA[16], AiA[16];
    {
        float xr = 0.f, xi = 0.f, Ar = 1.f, Ai = 0.f;
#pragma unroll
        for (int j = 0; j < 16; j++) {
            float dd = dt_s[lb + j] * step;
            float ee = s5_exp_small(lre * dd);
            float sn, cs;
            s5_sincos(lim * dd, sn, cs);
            float ar = ee * cs, ai = ee * sn;
            float arm1 = ar - 1.0f;
            float gr = (arm1 * lre + ai * lim) * inv;
            float gi = (ai * lre - arm1 * lim) * inv;
            float2 bu = *(const float2*)(Bu_s + (lb + j) * BUS + 2 * p);
            float br  = gr * bu.x - gi * bu.y;
            float bi2 = gr * bu.y + gi * bu.x;
            float nxr = ar * xr - ai * xi + br;
            float nxi = ar * xi + ai * xr + bi2;
            xr = nxr; xi = nxi;
            float nAr = ar * Ar - ai * Ai;
            float nAi = ar * Ai + ai * Ar;
            Ar = nAr; Ai = nAi;
            xrA[j] = xr; xiA[j] = xi; ArA[j] = Ar; AiA[j] = Ai;
        }
        As_s[seg * 64 + p]  = make_float2(Ar, Ai);
        xs_s2[seg * 64 + p] = make_float2(xr, xi);
    }
    __syncthreads();

    float cr = 0.f, ci = 0.f, pr = 1.f, pi = 0.f;
    for (int s = 0; s < seg; s++) {
        float2 A  = As_s[s * 64 + p];
        float2 xe = xs_s2[s * 64 + p];
        float ncr = A.x * cr - A.y * ci + xe.x;
        float nci = A.x * ci + A.y * cr + xe.y;
        cr = ncr; ci = nci;
        float npr = A.x * pr - A.y * pi;
        float npi = A.x * pi + A.y * pr;
        pr = npr; pi = npi;
    }

#pragma unroll
    for (int j = 0; j < 16; j++) {
        float xgR = ArA[j] * cr - AiA[j] * ci + xrA[j];
        float xgI = ArA[j] * ci + AiA[j] * cr + xiA[j];
        sc_xloc[(size_t)(l0 + lb + j) * P_DIM + gp] = make_float2(xgR, xgI);
    }
    if (seg == 3) {
        float AgR = pr * ArA[15] - pi * AiA[15];
        float AgI = pr * AiA[15] + pi * ArA[15];
        float xeR = ArA[15] * cr - AiA[15] * ci + xrA[15];
        float xeI = ArA[15] * ci + AiA[15] * cr + xiA[15];
        sc_AchunkT[gp * NCHUNK + blockIdx.y] = make_float2(AgR, AgI);
        sc_xendT[gp * NCHUNK + blockIdx.y]   = make_float2(xeR, xeI);
    }
}

// ---------- S2: PARALLEL scan over chunk aggregates ----------
__global__ __launch_bounds__(512) void s5_k2_chunkscan() {
    __shared__ __align__(16) float4 sdat[NCHUNK];
    int p = blockIdx.x;
    int t = threadIdx.x;
    float2 A = sc_AchunkT[p * NCHUNK + t];
    float2 X = sc_xendT[p * NCHUNK + t];
    sdat[t] = make_float4(A.x, A.y, X.x, X.y);
    __syncthreads();
#pragma unroll
    for (int off = 1; off < NCHUNK; off <<= 1) {
        float4 prev;
        bool has = (t >= off);
        if (has) prev = sdat[t - off];
        __syncthreads();
        if (has) {
            float4 cur = sdat[t];
            float4 nw;
            nw.x = cur.x * prev.x - cur.y * prev.y;
            nw.y = cur.x * prev.y + cur.y * prev.x;
            nw.z = cur.x * prev.z - cur.y * prev.w + cur.z;
            nw.w = cur.x * prev.w + cur.y * prev.z + cur.w;
            sdat[t] = nw;
        }
        __syncthreads();
    }
    float2 carry = make_float2(0.f, 0.f);
    if (t > 0) {
        float4 v = sdat[t - 1];
        carry = make_float2(v.z, v.w);
    }
    sc_carry[t * P_DIM + p] = carry;
}

// ---------- S3: analytic-Acum fixup + TENSOR readout y = X@W + D*u ----------
// occupancy 3 blocks/SM: 512 blocks -> 1.15 waves (was 1.73)
__global__ __launch_bounds__(256, 3) void s5_k3_fixup_gemm(
    const float* __restrict__ u, const float* __restrict__ D, float* __restrict__ out) {
    __shared__ __align__(16) char smem[40960];
    float* xs  = (float*)smem;                        // X hi [0,8192)
    float* wB0 = (float*)(smem + 8192);
    float* wB1 = (float*)(smem + 24576);

    int tid = threadIdx.x, tx = tid & 15, ty = tid >> 4;
    int lane = tid & 31, wid = tid >> 5;
    int gid = lane >> 2, tig = lane & 3;
    int wm = wid & 3, wn = wid >> 2;
    int chunk = blockIdx.x;
    int l0 = chunk * CHUNK;

    float d[8][4];
#pragma unroll
    for (int j = 0; j < 8; j++)
#pragma unroll
        for (int i = 0; i < 4; i++) d[j][i] = 0.0f;

    float2 Sr[4];
#pragma unroll
    for (int e = 0; e < 4; e++)
        Sr[e] = sc_S[chunk * CHUNK + 16 * e + ty];

    float2 pX[4], cC;
    float4 ab;
    auto ldgX = [&](int s) {
        int p0 = s * 16;
#pragma unroll
        for (int e = 0; e < 4; e++)
            pX[e] = sc_xloc[(size_t)(l0 + 16 * e + ty) * P_DIM + p0 + tx];
        cC = sc_carry[chunk * P_DIM + p0 + tx];
        ab = sc_ab4[p0 + tx];
    };
    auto stX = [&]() {
#pragma unroll
        for (int e = 0; e < 4; e++) {
            float Sh = Sr[e].x, Sl = Sr[e].y;
            float ph = ab.y * Sh;
            float pl = fmaf(ab.y, Sh, -ph);
            pl = fmaf(ab.y, Sl, pl);
            pl = fmaf(ab.z, Sh, pl);
            float amp = __expf(ab.x * Sh);
            float sn, cs;
            s5_sincos2(ph, pl, sn, cs);
            float Ar = amp * cs, Ai = amp * sn;
            float xre = Ar * cC.x - Ai * cC.y + pX[e].x;
            float xim = Ar * cC.y + Ai * cC.x + pX[e].y;
            int row = 16 * e + ty;
#pragma unroll
            for (int comp = 0; comp < 2; comp++) {
                float v = comp ? xim : xre;
                int k = comp * 16 + tx;
                int c = k & 7;
                int off = (k >> 3) * 512 + row * 8 + (c & 3) * 2 + (c >> 2);
                xs[off] = s5_tf32_rna(v);
            }
        }
    };
    auto cpW = [&](int s, int b) {
        float* wb = b ? wB1 : wB0;
        const float* src = &sc_Wt[s * 4096];
#pragma unroll
        for (int e = 0; e < 4; e++) {
            int q = e * 256 + tid;
            s5_cp16(&wb[q * 4], &src[q * 4]);
        }
        s5_cpcommit();
    };

    ldgX(0);
    cpW(0, 0);
    for (int s = 0; s < 16; s++) {
        int b = s & 1;
        stX();
        if (s < 15) { ldgX(s + 1); cpW(s + 1, b ^ 1); }
        if (s < 15) s5_cpwait<1>(); else s5_cpwait<0>();
        __syncthreads();
        const float* wb = b ? wB1 : wB0;
#pragma unroll
        for (int k8 = 0; k8 < 4; k8++) {
            int arow = wm * 16 + gid;
            float2 ah0 = *(const float2*)(xs + k8 * 512 + arow * 8 + tig * 2);
            float2 ah1 = *(const float2*)(xs + k8 * 512 + (arow + 8) * 8 + tig * 2);
            u32 ahi[4] = {__float_as_uint(ah0.x), __float_as_uint(ah1.x),
                          __float_as_uint(ah0.y), __float_as_uint(ah1.y)};
#pragma unroll
            for (int j = 0; j < 8; j++) {
                float2 bv = *(const float2*)(wb + k8 * 1024 + (wn * 64 + j * 8 + gid) * 8 + tig * 2);
                S5_MMA(d[j], ahi, __float_as_uint(bv.x), __float_as_uint(bv.y));
            }
        }
        __syncthreads();
    }

#pragma unroll
    for (int j = 0; j < 8; j++) {
        int h = wn * 64 + j * 8 + tig * 2;
        float2 Dv = *(const float2*)(D + h);
        int r1 = l0 + wm * 16 + gid;
        int r2 = r1 + 8;
        float2 u1 = *(const float2*)(u + (size_t)r1 * H_DIM + h);
        float2 u2 = *(const float2*)(u + (size_t)r2 * H_DIM + h);
        float2 y1, y2;
        y1.x = d[j][0] + Dv.x * u1.x;
        y1.y = d[j][1] + Dv.y * u1.y;
        y2.x = d[j][2] + Dv.x * u2.x;
        y2.y = d[j][3] + Dv.y * u2.y;
        *(float2*)(out + (size_t)r1 * H_DIM + h) = y1;
        *(float2*)(out + (size_t)r2 * H_DIM + h) = y2;
    }
}

extern "C" void kernel_launch(void* const* d_in, const int* in_sizes, int n_in,
                              void* d_out, int out_size) {
    const float* u       = (const float*)d_in[0];
    const float* dts     = (const float*)d_in[1];
    const float* Lre     = (const float*)d_in[2];
    const float* Lim     = (const float*)d_in[3];
    const float* logstep = (const float*)d_in[4];
    const float* Br      = (const float*)d_in[5];
    const float* Bi      = (const float*)d_in[6];
    const float* Cr      = (const float*)d_in[7];
    const float* Ci      = (const float*)d_in[8];
    const float* D       = (const float*)d_in[9];
    float* out = (float*)d_out;

    s5_k0_pack<<<(H_DIM * P_DIM + 255) / 256, 256>>>(Br, Bi, Cr, Ci, Lre, Lim, logstep);
    s5_kS_prefix<<<NCHUNK, CHUNK>>>(dts);
    dim3 g1(P_DIM / PTILE, L_SEQ / CHUNK);
    s5_k1_gemm_scan<<<g1, 256>>>(u, dts, Lre, Lim, logstep);
    s5_k2_chunkscan<<<P_DIM, NCHUNK>>>();
    s5_k3_fixup_gemm<<<L_SEQ / CHUNK, 256>>>(u, D, out);
}

// round 16
// speedup vs baseline: 1.0459x; 1.0459x over previous
#include <cuda_runtime.h>
#include <math.h>

#define L_SEQ 32768
#define H_DIM 128
#define P_DIM 256
#define CHUNK 64
#define NCHUNK (L_SEQ / CHUNK)   // 512
#define PTILE 64
#define BUS 136                   // padded float stride of Bu tile in smem

typedef unsigned long long u64;
typedef unsigned int u32;

// ---------- cp.async helpers ----------
__device__ __forceinline__ void s5_cp16(void* dst, const void* src) {
    unsigned d = (unsigned)__cvta_generic_to_shared(dst);
    asm volatile("cp.async.cg.shared.global [%0], [%1], 16;" :: "r"(d), "l"(src));
}
__device__ __forceinline__ void s5_cpcommit() {
    asm volatile("cp.async.commit_group;");
}
template <int N>
__device__ __forceinline__ void s5_cpwait() {
    asm volatile("cp.async.wait_group %0;" :: "n"(N));
}

// ---------- tf32 helpers ----------
__device__ __forceinline__ float s5_tf32_rna(float v) {
    u32 h;
    asm("cvt.rna.tf32.f32 %0, %1;" : "=r"(h) : "f"(v));
    return __uint_as_float(h);
}
#define S5_MMA(d, a, b0v, b1v) \
    asm volatile("mma.sync.aligned.m16n8k8.row.col.f32.tf32.tf32.f32 " \
                 "{%0,%1,%2,%3},{%4,%5,%6,%7},{%8,%9},{%0,%1,%2,%3};" \
                 : "+f"((d)[0]), "+f"((d)[1]), "+f"((d)[2]), "+f"((d)[3]) \
                 : "r"((a)[0]), "r"((a)[1]), "r"((a)[2]), "r"((a)[3]), \
                   "r"(b0v), "r"(b1v))

// ---------- fast math (validated ranges) ----------
__device__ __forceinline__ float s5_exp_small(float x) {   // x in [-0.06, 0]
    return fmaf(x, fmaf(x, fmaf(x, fmaf(x, 0.041666667f, 0.16666667f), 0.5f), 1.0f), 1.0f);
}
__device__ __forceinline__ void s5_sincos(float x, float& s_out, float& c_out) {
    float kf = rintf(x * 0.636619772f);                 // 2/pi
    float r = fmaf(-kf, 1.57079637f, x);
    r = fmaf(kf, 4.37113900e-8f, r);
    int q = (int)kf;
    float r2 = r * r;
    float sp = fmaf(r2, fmaf(r2, fmaf(r2, 2.7557314e-6f, -1.9841270e-4f),
                             8.3333310e-3f), -0.16666667f);
    sp = fmaf(r * r2, sp, r);
    float cp = fmaf(r2, fmaf(r2, fmaf(r2, 2.4801587e-5f, -1.3888889e-3f),
                             4.1666668e-2f), -0.5f);
    cp = fmaf(r2, cp, 1.0f);
    bool swp = (q & 1);
    float ss = swp ? cp : sp;
    float cc = swp ? sp : cp;
    if (q & 2) ss = -ss;
    if ((q + 1) & 2) cc = -cc;
    s_out = ss; c_out = cc;
}

// ---------- scratch (static device memory; no allocations) ----------
__device__ __align__(16) float2 sc_xloc[(size_t)L_SEQ * P_DIM];   // 64 MB
__device__ __align__(16) float2 sc_Acum[(size_t)L_SEQ * P_DIM];   // 64 MB (stored again; R9/R10 showed load beats recompute)
__device__ __align__(16) float2 sc_AchunkT[P_DIM * NCHUNK];       // [p][chunk]
__device__ __align__(16) float2 sc_xendT[P_DIM * NCHUNK];         // [p][chunk]
__device__ __align__(16) float2 sc_carry[NCHUNK * P_DIM];         // [chunk][p]
// k3 tensor operand: W = [2*Cr ; -2*Ci], tf32-RNE, fragment-permuted
__device__ __align__(16) float sc_Wt[16 * 4 * H_DIM * 8];         // 256 KB
// k1 tensor operand: WB[ptile(4)][s(4)][k8(4)][col(128)][sub(8)], col = 2*pl + (re/im)
__device__ __align__(16) float sc_WB[4 * 4 * 4 * 128 * 8];        // 256 KB

// ---------- S0: pack/permute operands ----------
__global__ void s5_k0_pack(const float* __restrict__ Br, const float* __restrict__ Bi,
                           const float* __restrict__ Cr, const float* __restrict__ Ci) {
    int idx = blockIdx.x * blockDim.x + threadIdx.x;
    if (idx < H_DIM * P_DIM) {
        int h = idx & 127, p = idx >> 7;
        {   // Wt (k3 operand)
            int s = p >> 4, pp = p & 15;
            int c = pp & 7;
            int sub = (c & 3) * 2 + (c >> 2);
            int k8r = pp >> 3;
            int k8i = 2 + (pp >> 3);
            float cr = Cr[h * P_DIM + p];
            float ci = Ci[h * P_DIM + p];
            sc_Wt[s * 4096 + k8r * 1024 + h * 8 + sub] = s5_tf32_rna(2.0f * cr);
            sc_Wt[s * 4096 + k8i * 1024 + h * 8 + sub] = s5_tf32_rna(-2.0f * ci);
        }
        {   // WB (k1 operand)
            int pt = p >> 6, pl = p & 63;
            int s = h >> 5, hk = h & 31;
            int k8 = hk >> 3, c = hk & 7;
            int sub = (c & 3) * 2 + (c >> 2);
            size_t base = ((size_t)(pt * 4 + s) * 4 + k8) * 1024;
            sc_WB[base + (pl * 2 + 0) * 8 + sub] = s5_tf32_rna(Br[p * H_DIM + h]);
            sc_WB[base + (pl * 2 + 1) * 8 + sub] = s5_tf32_rna(Bi[p * H_DIM + h]);
        }
    }
}

// ---------- S1: TENSOR Bu = u @ [Br|Bi]^T, then 4-way-parallel local scan ----------
__global__ __launch_bounds__(256, 2) void s5_k1_gemm_scan(
    const float* __restrict__ u, const float* __restrict__ dts,
    const float* __restrict__ Lre, const float* __restrict__ Lim,
    const float* __restrict__ logstep) {
    __shared__ __align__(16) char smem[40960];
    float* xs  = (float*)smem;                        // u hi [0,8192)
    float* wB0 = (float*)(smem + 8192);               // WB slice buf 0 (16 KB)
    float* wB1 = (float*)(smem + 24576);
    // scan-phase aliases
    float* Bu_s  = (float*)smem;                      // 64 x BUS floats (34816 B)
    float* dt_s  = (float*)(smem + 34816);            // 256 B
    float2* As_s  = (float2*)(smem + 35072);          // 2 KB
    float2* xs_s2 = (float2*)(smem + 37120);          // 2 KB

    int tid = threadIdx.x;
    int lane = tid & 31, wid = tid >> 5;
    int gid = lane >> 2, tig = lane & 3;
    int wm = wid & 3, wn = wid >> 2;
    int l0 = blockIdx.y * CHUNK;
    int pt = blockIdx.x;
    int p0 = pt * PTILE;

    float d[8][4];
#pragma unroll
    for (int j = 0; j < 8; j++)
#pragma unroll
        for (int i = 0; i < 4; i++) d[j][i] = 0.0f;

    float ur[8];
    auto ldgU = [&](int s) {
        int h0 = s * 32;
#pragma unroll
        for (int e = 0; e < 8; e++) {
            int idx = e * 256 + tid;
            int row = idx >> 5, k = idx & 31;
            ur[e] = u[(size_t)(l0 + row) * H_DIM + h0 + k];
        }
    };
    auto stU = [&]() {
#pragma unroll
        for (int e = 0; e < 8; e++) {
            int idx = e * 256 + tid;
            int row = idx >> 5, k = idx & 31;
            int c = k & 7;
            int off = (k >> 3) * 512 + row * 8 + (c & 3) * 2 + (c >> 2);
            xs[off] = s5_tf32_rna(ur[e]);
        }
    };
    auto cpW = [&](int s, int b) {
        float* wb = b ? wB1 : wB0;
        const float* src = &sc_WB[(size_t)(pt * 4 + s) * 4096];
#pragma unroll
        for (int e = 0; e < 4; e++) {
            int q = e * 256 + tid;
            s5_cp16(&wb[q * 4], &src[q * 4]);
        }
        s5_cpcommit();
    };

    ldgU(0);
    cpW(0, 0);
#pragma unroll
    for (int s = 0; s < 4; s++) {
        int b = s & 1;
        stU();
        if (s < 3) { ldgU(s + 1); cpW(s + 1, b ^ 1); }
        if (s < 3) s5_cpwait<1>(); else s5_cpwait<0>();
        __syncthreads();
        const float* wb = b ? wB1 : wB0;
#pragma unroll
        for (int k8 = 0; k8 < 4; k8++) {
            int arow = wm * 16 + gid;
            float2 ah0 = *(const float2*)(xs + k8 * 512 + arow * 8 + tig * 2);
            float2 ah1 = *(const float2*)(xs + k8 * 512 + (arow + 8) * 8 + tig * 2);
            u32 ahi[4] = {__float_as_uint(ah0.x), __float_as_uint(ah1.x),
                          __float_as_uint(ah0.y), __float_as_uint(ah1.y)};
#pragma unroll
            for (int j = 0; j < 8; j++) {
                float2 bv = *(const float2*)(wb + k8 * 1024 + (wn * 64 + j * 8 + gid) * 8 + tig * 2);
                S5_MMA(d[j], ahi, __float_as_uint(bv.x), __float_as_uint(bv.y));
            }
        }
        __syncthreads();
    }

    // write Bu tile into padded smem + dt
#pragma unroll
    for (int j = 0; j < 8; j++) {
        int cc = wn * 64 + j * 8 + tig * 2;
        int r1 = wm * 16 + gid;
        *(float2*)(Bu_s + r1 * BUS + cc)       = make_float2(d[j][0], d[j][1]);
        *(float2*)(Bu_s + (r1 + 8) * BUS + cc) = make_float2(d[j][2], d[j][3]);
    }
    if (tid < CHUNK) dt_s[tid] = dts[l0 + tid];
    __syncthreads();

    // ---- parallel local scan: 64 p-columns x 4 segments of 16 steps ----
    int p   = tid & 63;
    int seg = tid >> 6;
    int gp  = p0 + p;
    int lb  = seg * 16;
    float lre = Lre[gp], lim = Lim[gp];
    float step = expf(logstep[gp]);
    float inv = 1.0f / (lre * lre + lim * lim);

    float xrA[16], xiA[16], ArA[16], AiA[16];
    {
        float xr = 0.f, xi = 0.f, Ar = 1.f, Ai = 0.f;
#pragma unroll
        for (int j = 0; j < 16; j++) {
            float dd = dt_s[lb + j] * step;
            float ee = s5_exp_small(lre * dd);
            float sn, cs;
            s5_sincos(lim * dd, sn, cs);
            float ar = ee * cs, ai = ee * sn;
            float arm1 = ar - 1.0f;
            float gr = (arm1 * lre + ai * lim) * inv;
            float gi = (ai * lre - arm1 * lim) * inv;
            float2 bu = *(const float2*)(Bu_s + (lb + j) * BUS + 2 * p);
            float br  = gr * bu.x - gi * bu.y;
            float bi2 = gr * bu.y + gi * bu.x;
            float nxr = ar * xr - ai * xi + br;
            float nxi = ar * xi + ai * xr + bi2;
            xr = nxr; xi = nxi;
            float nAr = ar * Ar - ai * Ai;
            float nAi = ar * Ai + ai * Ar;
            Ar = nAr; Ai = nAi;
            xrA[j] = xr; xiA[j] = xi; ArA[j] = Ar; AiA[j] = Ai;
        }
        As_s[seg * 64 + p]  = make_float2(Ar, Ai);
        xs_s2[seg * 64 + p] = make_float2(xr, xi);
    }
    __syncthreads();

    float cr = 0.f, ci = 0.f, pr = 1.f, pi = 0.f;
    for (int s = 0; s < seg; s++) {
        float2 A  = As_s[s * 64 + p];
        float2 xe = xs_s2[s * 64 + p];
        float ncr = A.x * cr - A.y * ci + xe.x;
        float nci = A.x * ci + A.y * cr + xe.y;
        cr = ncr; ci = nci;
        float npr = A.x * pr - A.y * pi;
        float npi = A.x * pi + A.y * pr;
        pr = npr; pi = npi;
    }

    // store chunk-relative states AND chunk-global Acum (k3 loads both)
    float lastAr = 0.f, lastAi = 0.f, lastXr = 0.f, lastXi = 0.f;
#pragma unroll
    for (int j = 0; j < 16; j++) {
        float AgR = pr * ArA[j] - pi * AiA[j];
        float AgI = pr * AiA[j] + pi * ArA[j];
        float xgR = ArA[j] * cr - AiA[j] * ci + xrA[j];
        float xgI = ArA[j] * ci + AiA[j] * cr + xiA[j];
        size_t g = (size_t)(l0 + lb + j) * P_DIM + gp;
        sc_xloc[g] = make_float2(xgR, xgI);
        sc_Acum[g] = make_float2(AgR, AgI);
        if (j == 15) { lastAr = AgR; lastAi = AgI; lastXr = xgR; lastXi = xgI; }
    }
    if (seg == 3) {
        sc_AchunkT[gp * NCHUNK + blockIdx.y] = make_float2(lastAr, lastAi);
        sc_xendT[gp * NCHUNK + blockIdx.y]   = make_float2(lastXr, lastXi);
    }
}

// ---------- S2: PARALLEL scan over chunk aggregates ----------
__global__ __launch_bounds__(512) void s5_k2_chunkscan() {
    __shared__ __align__(16) float4 sdat[NCHUNK];
    int p = blockIdx.x;
    int t = threadIdx.x;
    float2 A = sc_AchunkT[p * NCHUNK + t];
    float2 X = sc_xendT[p * NCHUNK + t];
    sdat[t] = make_float4(A.x, A.y, X.x, X.y);
    __syncthreads();
#pragma unroll
    for (int off = 1; off < NCHUNK; off <<= 1) {
        float4 prev;
        bool has = (t >= off);
        if (has) prev = sdat[t - off];
        __syncthreads();
        if (has) {
            float4 cur = sdat[t];
            float4 nw;
            nw.x = cur.x * prev.x - cur.y * prev.y;
            nw.y = cur.x * prev.y + cur.y * prev.x;
            nw.z = cur.x * prev.z - cur.y * prev.w + cur.z;
            nw.w = cur.x * prev.w + cur.y * prev.z + cur.w;
            sdat[t] = nw;
        }
        __syncthreads();
    }
    float2 carry = make_float2(0.f, 0.f);
    if (t > 0) {
        float4 v = sdat[t - 1];
        carry = make_float2(v.z, v.w);
    }
    sc_carry[t * P_DIM + p] = carry;
}

// ---------- S3: stored-Acum fixup + TENSOR readout y = X@W + D*u ----------
__global__ __launch_bounds__(256, 2) void s5_k3_fixup_gemm(
    const float* __restrict__ u, const float* __restrict__ D, float* __restrict__ out) {
    __shared__ __align__(16) char smem[40960];
    float* xs  = (float*)smem;                        // X hi [0,8192)
    float* wB0 = (float*)(smem + 8192);
    float* wB1 = (float*)(smem + 24576);

    int tid = threadIdx.x, tx = tid & 15, ty = tid >> 4;
    int lane = tid & 31, wid = tid >> 5;
    int gid = lane >> 2, tig = lane & 3;
    int wm = wid & 3, wn = wid >> 2;
    int chunk = blockIdx.x;
    int l0 = chunk * CHUNK;

    float d[8][4];
#pragma unroll
    for (int j = 0; j < 8; j++)
#pragma unroll
        for (int i = 0; i < 4; i++) d[j][i] = 0.0f;

    float2 pX[4], pA[4], cC;
    auto ldgX = [&](int s) {
        int p0 = s * 16;
#pragma unroll
        for (int e = 0; e < 4; e++) {
            size_t g = (size_t)(l0 + 16 * e + ty) * P_DIM + p0 + tx;
            pX[e] = sc_xloc[g];
            pA[e] = sc_Acum[g];
        }
        cC = sc_carry[chunk * P_DIM + p0 + tx];
    };
    auto stX = [&]() {
#pragma unroll
        for (int e = 0; e < 4; e++) {
            float xre = pA[e].x * cC.x - pA[e].y * cC.y + pX[e].x;
            float xim = pA[e].x * cC.y + pA[e].y * cC.x + pX[e].y;
            int row = 16 * e + ty;
#pragma unroll
            for (int comp = 0; comp < 2; comp++) {
                float v = comp ? xim : xre;
                int k = comp * 16 + tx;
                int c = k & 7;
                int off = (k >> 3) * 512 + row * 8 + (c & 3) * 2 + (c >> 2);
                xs[off] = s5_tf32_rna(v);
            }
        }
    };
    auto cpW = [&](int s, int b) {
        float* wb = b ? wB1 : wB0;
        const float* src = &sc_Wt[s * 4096];
#pragma unroll
        for (int e = 0; e < 4; e++) {
            int q = e * 256 + tid;
            s5_cp16(&wb[q * 4], &src[q * 4]);
        }
        s5_cpcommit();
    };

    ldgX(0);
    cpW(0, 0);
    for (int s = 0; s < 16; s++) {
        int b = s & 1;
        stX();
        if (s < 15) { ldgX(s + 1); cpW(s + 1, b ^ 1); }
        if (s < 15) s5_cpwait<1>(); else s5_cpwait<0>();
        __syncthreads();
        const float* wb = b ? wB1 : wB0;
#pragma unroll
        for (int k8 = 0; k8 < 4; k8++) {
            int arow = wm * 16 + gid;
            float2 ah0 = *(const float2*)(xs + k8 * 512 + arow * 8 + tig * 2);
            float2 ah1 = *(const float2*)(xs + k8 * 512 + (arow + 8) * 8 + tig * 2);
            u32 ahi[4] = {__float_as_uint(ah0.x), __float_as_uint(ah1.x),
                          __float_as_uint(ah0.y), __float_as_uint(ah1.y)};
#pragma unroll
            for (int j = 0; j < 8; j++) {
                float2 bv = *(const float2*)(wb + k8 * 1024 + (wn * 64 + j * 8 + gid) * 8 + tig * 2);
                S5_MMA(d[j], ahi, __float_as_uint(bv.x), __float_as_uint(bv.y));
            }
        }
        __syncthreads();
    }

#pragma unroll
    for (int j = 0; j < 8; j++) {
        int h = wn * 64 + j * 8 + tig * 2;
        float2 Dv = *(const float2*)(D + h);
        int r1 = l0 + wm * 16 + gid;
        int r2 = r1 + 8;
        float2 u1 = *(const float2*)(u + (size_t)r1 * H_DIM + h);
        float2 u2 = *(const float2*)(u + (size_t)r2 * H_DIM + h);
        float2 y1, y2;
        y1.x = d[j][0] + Dv.x * u1.x;
        y1.y = d[j][1] + Dv.y * u1.y;
        y2.x = d[j][2] + Dv.x * u2.x;
        y2.y = d[j][3] + Dv.y * u2.y;
        *(float2*)(out + (size_t)r1 * H_DIM + h) = y1;
        *(float2*)(out + (size_t)r2 * H_DIM + h) = y2;
    }
}

extern "C" void kernel_launch(void* const* d_in, const int* in_sizes, int n_in,
                              void* d_out, int out_size) {
    const float* u       = (const float*)d_in[0];
    const float* dts     = (const float*)d_in[1];
    const float* Lre     = (const float*)d_in[2];
    const float* Lim     = (const float*)d_in[3];
    const float* logstep = (const float*)d_in[4];
    const float* Br      = (const float*)d_in[5];
    const float* Bi      = (const float*)d_in[6];
    const float* Cr      = (const float*)d_in[7];
    const float* Ci      = (const float*)d_in[8];
    const float* D       = (const float*)d_in[9];
    float* out = (float*)d_out;

    s5_k0_pack<<<(H_DIM * P_DIM + 255) / 256, 256>>>(Br, Bi, Cr, Ci);
    dim3 g1(P_DIM / PTILE, L_SEQ / CHUNK);
    s5_k1_gemm_scan<<<g1, 256>>>(u, dts, Lre, Lim, logstep);
    s5_k2_chunkscan<<<P_DIM, NCHUNK>>>();
    s5_k3_fixup_gemm<<<L_SEQ / CHUNK, 256>>>(u, D, out);
}

// round 17
// speedup vs baseline: 1.1500x; 1.0995x over previous
#include <cuda_runtime.h>
#include <cuda_fp16.h>
#include <math.h>

#define L_SEQ 32768
#define H_DIM 128
#define P_DIM 256
#define CHUNK 64
#define NCHUNK (L_SEQ / CHUNK)   // 512
#define PTILE 64
#define BUS 136                   // padded float stride of Bu tile in smem

typedef unsigned long long u64;
typedef unsigned int u32;

// packed per-element state: (Acum, xloc) as 4 halves = 8 bytes
struct __align__(8) AX {
    __half2 A;
    __half2 x;
};

// ---------- cp.async helpers ----------
__device__ __forceinline__ void s5_cp16(void* dst, const void* src) {
    unsigned d = (unsigned)__cvta_generic_to_shared(dst);
    asm volatile("cp.async.cg.shared.global [%0], [%1], 16;" :: "r"(d), "l"(src));
}
__device__ __forceinline__ void s5_cpcommit() {
    asm volatile("cp.async.commit_group;");
}
template <int N>
__device__ __forceinline__ void s5_cpwait() {
    asm volatile("cp.async.wait_group %0;" :: "n"(N));
}

// ---------- tf32 helpers ----------
__device__ __forceinline__ float s5_tf32_rna(float v) {
    u32 h;
    asm("cvt.rna.tf32.f32 %0, %1;" : "=r"(h) : "f"(v));
    return __uint_as_float(h);
}
#define S5_MMA(d, a, b0v, b1v) \
    asm volatile("mma.sync.aligned.m16n8k8.row.col.f32.tf32.tf32.f32 " \
                 "{%0,%1,%2,%3},{%4,%5,%6,%7},{%8,%9},{%0,%1,%2,%3};" \
                 : "+f"((d)[0]), "+f"((d)[1]), "+f"((d)[2]), "+f"((d)[3]) \
                 : "r"((a)[0]), "r"((a)[1]), "r"((a)[2]), "r"((a)[3]), \
                   "r"(b0v), "r"(b1v))

// ---------- fast math (validated ranges) ----------
__device__ __forceinline__ float s5_exp_small(float x) {   // x in [-0.06, 0]
    return fmaf(x, fmaf(x, fmaf(x, fmaf(x, 0.041666667f, 0.16666667f), 0.5f), 1.0f), 1.0f);
}
__device__ __forceinline__ void s5_sincos(float x, float& s_out, float& c_out) {
    float kf = rintf(x * 0.636619772f);                 // 2/pi
    float r = fmaf(-kf, 1.57079637f, x);
    r = fmaf(kf, 4.37113900e-8f, r);
    int q = (int)kf;
    float r2 = r * r;
    float sp = fmaf(r2, fmaf(r2, fmaf(r2, 2.7557314e-6f, -1.9841270e-4f),
                             8.3333310e-3f), -0.16666667f);
    sp = fmaf(r * r2, sp, r);
    float cp = fmaf(r2, fmaf(r2, fmaf(r2, 2.4801587e-5f, -1.3888889e-3f),
                             4.1666668e-2f), -0.5f);
    cp = fmaf(r2, cp, 1.0f);
    bool swp = (q & 1);
    float ss = swp ? cp : sp;
    float cc = swp ? sp : cp;
    if (q & 2) ss = -ss;
    if ((q + 1) & 2) cc = -cc;
    s_out = ss; c_out = cc;
}

// ---------- scratch (static device memory; no allocations) ----------
__device__ __align__(16) AX sc_AX[(size_t)L_SEQ * P_DIM];         // 32 MB packed (A, x)
__device__ __align__(16) float2 sc_AchunkT[P_DIM * NCHUNK];       // [p][chunk]
__device__ __align__(16) float2 sc_xendT[P_DIM * NCHUNK];         // [p][chunk]
__device__ __align__(16) float2 sc_carry[NCHUNK * P_DIM];         // [chunk][p]
// k3 tensor operand: W = [2*Cr ; -2*Ci], tf32-RNE, fragment-permuted
__device__ __align__(16) float sc_Wt[16 * 4 * H_DIM * 8];         // 256 KB
// k1 tensor operand: WB[ptile(4)][s(4)][k8(4)][col(128)][sub(8)], col = 2*pl + (re/im)
__device__ __align__(16) float sc_WB[4 * 4 * 4 * 128 * 8];        // 256 KB

// ---------- S0: pack/permute operands ----------
__global__ void s5_k0_pack(const float* __restrict__ Br, const float* __restrict__ Bi,
                           const float* __restrict__ Cr, const float* __restrict__ Ci) {
    int idx = blockIdx.x * blockDim.x + threadIdx.x;
    if (idx < H_DIM * P_DIM) {
        int h = idx & 127, p = idx >> 7;
        {   // Wt (k3 operand)
            int s = p >> 4, pp = p & 15;
            int c = pp & 7;
            int sub = (c & 3) * 2 + (c >> 2);
            int k8r = pp >> 3;
            int k8i = 2 + (pp >> 3);
            float cr = Cr[h * P_DIM + p];
            float ci = Ci[h * P_DIM + p];
            sc_Wt[s * 4096 + k8r * 1024 + h * 8 + sub] = s5_tf32_rna(2.0f * cr);
            sc_Wt[s * 4096 + k8i * 1024 + h * 8 + sub] = s5_tf32_rna(-2.0f * ci);
        }
        {   // WB (k1 operand)
            int pt = p >> 6, pl = p & 63;
            int s = h >> 5, hk = h & 31;
            int k8 = hk >> 3, c = hk & 7;
            int sub = (c & 3) * 2 + (c >> 2);
            size_t base = ((size_t)(pt * 4 + s) * 4 + k8) * 1024;
            sc_WB[base + (pl * 2 + 0) * 8 + sub] = s5_tf32_rna(Br[p * H_DIM + h]);
            sc_WB[base + (pl * 2 + 1) * 8 + sub] = s5_tf32_rna(Bi[p * H_DIM + h]);
        }
    }
}

// ---------- S1: TENSOR Bu = u @ [Br|Bi]^T, then 4-way-parallel local scan ----------
__global__ __launch_bounds__(256, 2) void s5_k1_gemm_scan(
    const float* __restrict__ u, const float* __restrict__ dts,
    const float* __restrict__ Lre, const float* __restrict__ Lim,
    const float* __restrict__ logstep) {
    __shared__ __align__(16) char smem[40960];
    float* xs  = (float*)smem;                        // u hi [0,8192)
    float* wB0 = (float*)(smem + 8192);               // WB slice buf 0 (16 KB)
    float* wB1 = (float*)(smem + 24576);
    // scan-phase aliases
    float* Bu_s  = (float*)smem;                      // 64 x BUS floats (34816 B)
    float* dt_s  = (float*)(smem + 34816);            // 256 B
    float2* As_s  = (float2*)(smem + 35072);          // 2 KB
    float2* xs_s2 = (float2*)(smem + 37120);          // 2 KB

    int tid = threadIdx.x;
    int lane = tid & 31, wid = tid >> 5;
    int gid = lane >> 2, tig = lane & 3;
    int wm = wid & 3, wn = wid >> 2;
    int l0 = blockIdx.y * CHUNK;
    int pt = blockIdx.x;
    int p0 = pt * PTILE;

    float d[8][4];
#pragma unroll
    for (int j = 0; j < 8; j++)
#pragma unroll
        for (int i = 0; i < 4; i++) d[j][i] = 0.0f;

    float ur[8];
    auto ldgU = [&](int s) {
        int h0 = s * 32;
#pragma unroll
        for (int e = 0; e < 8; e++) {
            int idx = e * 256 + tid;
            int row = idx >> 5, k = idx & 31;
            ur[e] = u[(size_t)(l0 + row) * H_DIM + h0 + k];
        }
    };
    auto stU = [&]() {
#pragma unroll
        for (int e = 0; e < 8; e++) {
            int idx = e * 256 + tid;
            int row = idx >> 5, k = idx & 31;
            int c = k & 7;
            int off = (k >> 3) * 512 + row * 8 + (c & 3) * 2 + (c >> 2);
            xs[off] = s5_tf32_rna(ur[e]);
        }
    };
    auto cpW = [&](int s, int b) {
        float* wb = b ? wB1 : wB0;
        const float* src = &sc_WB[(size_t)(pt * 4 + s) * 4096];
#pragma unroll
        for (int e = 0; e < 4; e++) {
            int q = e * 256 + tid;
            s5_cp16(&wb[q * 4], &src[q * 4]);
        }
        s5_cpcommit();
    };

    ldgU(0);
    cpW(0, 0);
#pragma unroll
    for (int s = 0; s < 4; s++) {
        int b = s & 1;
        stU();
        if (s < 3) { ldgU(s + 1); cpW(s + 1, b ^ 1); }
        if (s < 3) s5_cpwait<1>(); else s5_cpwait<0>();
        __syncthreads();
        const float* wb = b ? wB1 : wB0;
#pragma unroll
        for (int k8 = 0; k8 < 4; k8++) {
            int arow = wm * 16 + gid;
            float2 ah0 = *(const float2*)(xs + k8 * 512 + arow * 8 + tig * 2);
            float2 ah1 = *(const float2*)(xs + k8 * 512 + (arow + 8) * 8 + tig * 2);
            u32 ahi[4] = {__float_as_uint(ah0.x), __float_as_uint(ah1.x),
                          __float_as_uint(ah0.y), __float_as_uint(ah1.y)};
#pragma unroll
            for (int j = 0; j < 8; j++) {
                float2 bv = *(const float2*)(wb + k8 * 1024 + (wn * 64 + j * 8 + gid) * 8 + tig * 2);
                S5_MMA(d[j], ahi, __float_as_uint(bv.x), __float_as_uint(bv.y));
            }
        }
        __syncthreads();
    }

    // write Bu tile into padded smem + dt
#pragma unroll
    for (int j = 0; j < 8; j++) {
        int cc = wn * 64 + j * 8 + tig * 2;
        int r1 = wm * 16 + gid;
        *(float2*)(Bu_s + r1 * BUS + cc)       = make_float2(d[j][0], d[j][1]);
        *(float2*)(Bu_s + (r1 + 8) * BUS + cc) = make_float2(d[j][2], d[j][3]);
    }
    if (tid < CHUNK) dt_s[tid] = dts[l0 + tid];
    __syncthreads();

    // ---- parallel local scan: 64 p-columns x 4 segments of 16 steps ----
    int p   = tid & 63;
    int seg = tid >> 6;
    int gp  = p0 + p;
    int lb  = seg * 16;
    float lre = Lre[gp], lim = Lim[gp];
    float step = expf(logstep[gp]);
    float inv = 1.0f / (lre * lre + lim * lim);

    float xrA[16], xiA[16], ArA[16], AiA[16];
    {
        float xr = 0.f, xi = 0.f, Ar = 1.f, Ai = 0.f;
#pragma unroll
        for (int j = 0; j < 16; j++) {
            float dd = dt_s[lb + j] * step;
            float ee = s5_exp_small(lre * dd);
            float sn, cs;
            s5_sincos(lim * dd, sn, cs);
            float ar = ee * cs, ai = ee * sn;
            float arm1 = ar - 1.0f;
            float gr = (arm1 * lre + ai * lim) * inv;
            float gi = (ai * lre - arm1 * lim) * inv;
            float2 bu = *(const float2*)(Bu_s + (lb + j) * BUS + 2 * p);
            float br  = gr * bu.x - gi * bu.y;
            float bi2 = gr * bu.y + gi * bu.x;
            float nxr = ar * xr - ai * xi + br;
            float nxi = ar * xi + ai * xr + bi2;
            xr = nxr; xi = nxi;
            float nAr = ar * Ar - ai * Ai;
            float nAi = ar * Ai + ai * Ar;
            Ar = nAr; Ai = nAi;
            xrA[j] = xr; xiA[j] = xi; ArA[j] = Ar; AiA[j] = Ai;
        }
        As_s[seg * 64 + p]  = make_float2(Ar, Ai);
        xs_s2[seg * 64 + p] = make_float2(xr, xi);
    }
    __syncthreads();

    float cr = 0.f, ci = 0.f, pr = 1.f, pi = 0.f;
    for (int s = 0; s < seg; s++) {
        float2 A  = As_s[s * 64 + p];
        float2 xe = xs_s2[s * 64 + p];
        float ncr = A.x * cr - A.y * ci + xe.x;
        float nci = A.x * ci + A.y * cr + xe.y;
        cr = ncr; ci = nci;
        float npr = A.x * pr - A.y * pi;
        float npi = A.x * pi + A.y * pr;
        pr = npr; pi = npi;
    }

    // store packed fp16 (Acum, xloc); fp16 mantissa == tf32 mantissa used by k3's MMA
    float lastAr = 0.f, lastAi = 0.f, lastXr = 0.f, lastXi = 0.f;
#pragma unroll
    for (int j = 0; j < 16; j++) {
        float AgR = pr * ArA[j] - pi * AiA[j];
        float AgI = pr * AiA[j] + pi * ArA[j];
        float xgR = ArA[j] * cr - AiA[j] * ci + xrA[j];
        float xgI = ArA[j] * ci + AiA[j] * cr + xiA[j];
        AX v;
        v.A = __floats2half2_rn(AgR, AgI);
        v.x = __floats2half2_rn(xgR, xgI);
        sc_AX[(size_t)(l0 + lb + j) * P_DIM + gp] = v;
        if (j == 15) { lastAr = AgR; lastAi = AgI; lastXr = xgR; lastXi = xgI; }
    }
    if (seg == 3) {
        sc_AchunkT[gp * NCHUNK + blockIdx.y] = make_float2(lastAr, lastAi);
        sc_xendT[gp * NCHUNK + blockIdx.y]   = make_float2(lastXr, lastXi);
    }
}

// ---------- S2: PARALLEL scan over chunk aggregates ----------
__global__ __launch_bounds__(512) void s5_k2_chunkscan() {
    __shared__ __align__(16) float4 sdat[NCHUNK];
    int p = blockIdx.x;
    int t = threadIdx.x;
    float2 A = sc_AchunkT[p * NCHUNK + t];
    float2 X = sc_xendT[p * NCHUNK + t];
    sdat[t] = make_float4(A.x, A.y, X.x, X.y);
    __syncthreads();
#pragma unroll
    for (int off = 1; off < NCHUNK; off <<= 1) {
        float4 prev;
        bool has = (t >= off);
        if (has) prev = sdat[t - off];
        __syncthreads();
        if (has) {
            float4 cur = sdat[t];
            float4 nw;
            nw.x = cur.x * prev.x - cur.y * prev.y;
            nw.y = cur.x * prev.y + cur.y * prev.x;
            nw.z = cur.x * prev.z - cur.y * prev.w + cur.z;
            nw.w = cur.x * prev.w + cur.y * prev.z + cur.w;
            sdat[t] = nw;
        }
        __syncthreads();
    }
    float2 carry = make_float2(0.f, 0.f);
    if (t > 0) {
        float4 v = sdat[t - 1];
        carry = make_float2(v.z, v.w);
    }
    sc_carry[t * P_DIM + p] = carry;
}

// ---------- S3: packed-fp16 fixup + TENSOR readout y = X@W + D*u ----------
__global__ __launch_bounds__(256, 2) void s5_k3_fixup_gemm(
    const float* __restrict__ u, const float* __restrict__ D, float* __restrict__ out) {
    __shared__ __align__(16) char smem[40960];
    float* xs  = (float*)smem;                        // X hi [0,8192)
    float* wB0 = (float*)(smem + 8192);
    float* wB1 = (float*)(smem + 24576);

    int tid = threadIdx.x, tx = tid & 15, ty = tid >> 4;
    int lane = tid & 31, wid = tid >> 5;
    int gid = lane >> 2, tig = lane & 3;
    int wm = wid & 3, wn = wid >> 2;
    int chunk = blockIdx.x;
    int l0 = chunk * CHUNK;

    float d[8][4];
#pragma unroll
    for (int j = 0; j < 8; j++)
#pragma unroll
        for (int i = 0; i < 4; i++) d[j][i] = 0.0f;

    AX pV[4];
    float2 cC;
    auto ldgX = [&](int s) {
        int p0 = s * 16;
#pragma unroll
        for (int e = 0; e < 4; e++)
            pV[e] = sc_AX[(size_t)(l0 + 16 * e + ty) * P_DIM + p0 + tx];
        cC = sc_carry[chunk * P_DIM + p0 + tx];
    };
    auto stX = [&]() {
#pragma unroll
        for (int e = 0; e < 4; e++) {
            float2 A  = __half22float2(pV[e].A);
            float2 xl = __half22float2(pV[e].x);
            float xre = A.x * cC.x - A.y * cC.y + xl.x;
            float xim = A.x * cC.y + A.y * cC.x + xl.y;
            int row = 16 * e + ty;
#pragma unroll
            for (int comp = 0; comp < 2; comp++) {
                float v = comp ? xim : xre;
                int k = comp * 16 + tx;
                int c = k & 7;
                int off = (k >> 3) * 512 + row * 8 + (c & 3) * 2 + (c >> 2);
                xs[off] = s5_tf32_rna(v);
            }
        }
    };
    auto cpW = [&](int s, int b) {
        float* wb = b ? wB1 : wB0;
        const float* src = &sc_Wt[s * 4096];
#pragma unroll
        for (int e = 0; e < 4; e++) {
            int q = e * 256 + tid;
            s5_cp16(&wb[q * 4], &src[q * 4]);
        }
        s5_cpcommit();
    };

    ldgX(0);
    cpW(0, 0);
    for (int s = 0; s < 16; s++) {
        int b = s & 1;
        stX();
        if (s < 15) { ldgX(s + 1); cpW(s + 1, b ^ 1); }
        if (s < 15) s5_cpwait<1>(); else s5_cpwait<0>();
        __syncthreads();
        const float* wb = b ? wB1 : wB0;
#pragma unroll
        for (int k8 = 0; k8 < 4; k8++) {
            int arow = wm * 16 + gid;
            float2 ah0 = *(const float2*)(xs + k8 * 512 + arow * 8 + tig * 2);
            float2 ah1 = *(const float2*)(xs + k8 * 512 + (arow + 8) * 8 + tig * 2);
            u32 ahi[4] = {__float_as_uint(ah0.x), __float_as_uint(ah1.x),
                          __float_as_uint(ah0.y), __float_as_uint(ah1.y)};
#pragma unroll
            for (int j = 0; j < 8; j++) {
                float2 bv = *(const float2*)(wb + k8 * 1024 + (wn * 64 + j * 8 + gid) * 8 + tig * 2);
                S5_MMA(d[j], ahi, __float_as_uint(bv.x), __float_as_uint(bv.y));
            }
        }
        __syncthreads();
    }

#pragma unroll
    for (int j = 0; j < 8; j++) {
        int h = wn * 64 + j * 8 + tig * 2;
        float2 Dv = *(const float2*)(D + h);
        int r1 = l0 + wm * 16 + gid;
        int r2 = r1 + 8;
        float2 u1 = *(const float2*)(u + (size_t)r1 * H_DIM + h);
        float2 u2 = *(const float2*)(u + (size_t)r2 * H_DIM + h);
        float2 y1, y2;
        y1.x = d[j][0] + Dv.x * u1.x;
        y1.y = d[j][1] + Dv.y * u1.y;
        y2.x = d[j][2] + Dv.x * u2.x;
        y2.y = d[j][3] + Dv.y * u2.y;
        *(float2*)(out + (size_t)r1 * H_DIM + h) = y1;
        *(float2*)(out + (size_t)r2 * H_DIM + h) = y2;
    }
}

extern "C" void kernel_launch(void* const* d_in, const int* in_sizes, int n_in,
                              void* d_out, int out_size) {
    const float* u       = (const float*)d_in[0];
    const float* dts     = (const float*)d_in[1];
    const float* Lre     = (const float*)d_in[2];
    const float* Lim     = (const float*)d_in[3];
    const float* logstep = (const float*)d_in[4];
    const float* Br      = (const float*)d_in[5];
    const float* Bi      = (const float*)d_in[6];
    const float* Cr      = (const float*)d_in[7];
    const float* Ci      = (const float*)d_in[8];
    const float* D       = (const float*)d_in[9];
    float* out = (float*)d_out;

    s5_k0_pack<<<(H_DIM * P_DIM + 255) / 256, 256>>>(Br, Bi, Cr, Ci);
    dim3 g1(P_DIM / PTILE, L_SEQ / CHUNK);
    s5_k1_gemm_scan<<<g1, 256>>>(u, dts, Lre, Lim, logstep);
    s5_k2_chunkscan<<<P_DIM, NCHUNK>>>();
    s5_k3_fixup_gemm<<<L_SEQ / CHUNK, 256>>>(u, D, out);
}